// round 1
// baseline (speedup 1.0000x reference)
#include <cuda_runtime.h>
#include <cstdio>

// Problem constants
#define NB 8
#define NT 4096
#define NN 1024
#define NP (NB*NT)      // 32768 points
#define NU 256          // unknown nodes
#define NKMAX 768       // max known neighbors per row

// ---------------- scratch (device globals; allocation-free) ----------------
__device__ float g_deg[NN];
__device__ int   g_rank[NN];          // node -> unknown rank, or -1
__device__ float g_c[NU];             // sum_{j>=i} A[u_i,u_j]
__device__ float g_invdeg[NU];        // 1/deg[u_i]
__device__ int   g_Kcol[NU*NKMAX];    // known-neighbor node ids per unknown
__device__ int   g_Kcnt[NU];
__device__ int   g_Lcol[NU*NU];       // earlier-unknown neighbor ranks per unknown
__device__ int   g_Lcnt[NU];
__device__ float g_RT[(size_t)NU*NP]; // RHS, transposed [i][p]  (32 MB)
__device__ float g_VT[(size_t)NU*NP]; // solution, transposed [i][p] (32 MB)

// ---------------- k_deg: deg[n] = sum_m A[n,m] ----------------
__global__ void k_deg(const float* __restrict__ A) {
    int n = blockIdx.x;
    float s = 0.f;
    for (int m = threadIdx.x; m < NN; m += 256) s += A[n*NN + m];
    __shared__ float sh[256];
    sh[threadIdx.x] = s; __syncthreads();
    for (int o = 128; o > 0; o >>= 1) {
        if (threadIdx.x < o) sh[threadIdx.x] += sh[threadIdx.x + o];
        __syncthreads();
    }
    if (threadIdx.x == 0) g_deg[n] = sh[0];
}

// ---------------- rank init + scatter ----------------
__global__ void k_rank_init() {
    int t = blockIdx.x*256 + threadIdx.x;
    if (t < NN) g_rank[t] = -1;
}
__global__ void k_rank_set(const int* __restrict__ unk) {
    int i = threadIdx.x;                  // 256 threads
    g_rank[unk[i]] = i;
}

// ---------------- k_prep: build CSR rows (deterministic serial scan) -------
__global__ void k_prep(const float* __restrict__ A, const int* __restrict__ unk) {
    int i = threadIdx.x;                  // one block, 256 threads, thread = row
    int ui = unk[i];
    const float* row = A + (size_t)ui * NN;
    int kc = 0, lc = 0; float c = 0.f;
    for (int n = 0; n < NN; n++) {
        float a = row[n];
        if (a != 0.f) {
            int r = g_rank[n];
            if (r < 0)        g_Kcol[i*NKMAX + (kc++)] = n;
            else if (r < i)   g_Lcol[i*NU    + (lc++)] = r;
            else              c += a;     // r >= i (includes self, A[u,u]=1)
        }
    }
    g_Kcnt[i] = kc; g_Lcnt[i] = lc; g_c[i] = c;
    g_invdeg[i] = 1.f / g_deg[ui];
}

// ---------------- k_rhs: RT[i][p] = (sum_known x + mask*c_i) * invdeg_i ----
// Block: 256 threads (8 warps), 32 points. smem: x transposed [col][p], pad 33.
__global__ void k_rhs(const float* __restrict__ x, const float* __restrict__ maskp) {
    extern __shared__ float sx[];                 // [NN][33]
    int pbase = blockIdx.x * 32;
    // load 32 x-rows, transposed (coalesced LDG, conflict-free STS)
    for (int idx = threadIdx.x; idx < 32*NN; idx += 256) {
        int p = idx >> 10, n = idx & (NN-1);
        sx[n*33 + p] = x[(size_t)(pbase + p)*NN + n];
    }
    __syncthreads();
    float mask = *maskp;
    int lane = threadIdx.x & 31, w = threadIdx.x >> 5;
    for (int i = w; i < NU; i += 8) {
        int cnt = g_Kcnt[i];
        const int* kc = &g_Kcol[i*NKMAX];
        float acc = 0.f;
        for (int s = 0; s < cnt; s++) {
            int col = __ldg(&kc[s]);              // uniform across warp
            acc += sx[col*33 + lane];             // bank = (col+lane)%32: conflict-free
        }
        float r = (acc + mask * g_c[i]) * g_invdeg[i];
        g_RT[(size_t)i*NP + pbase + lane] = r;    // coalesced per warp
    }
}

// ---------------- k_solve: per-point sequential sparse triangular solve ----
// Block: 128 threads = 128 points. smem y: [i][tid] -> conflict-free, uniform i.
__global__ void k_solve() {
    extern __shared__ float y[];                  // [NU][128]
    int t = threadIdx.x;
    size_t p = (size_t)blockIdx.x * 128 + t;
    for (int i = 0; i < NU; i++) {
        float acc = g_RT[(size_t)i*NP + p];       // coalesced
        int cnt = g_Lcnt[i];
        const int* lc = &g_Lcol[i*NU];
        float s = 0.f;
        for (int k = 0; k < cnt; k++)
            s += y[__ldg(&lc[k])*128 + t];        // uniform index -> no conflicts
        acc += s * g_invdeg[i];
        y[i*128 + t] = acc;
        g_VT[(size_t)i*NP + p] = acc;             // coalesced
    }
}

// ---------------- k_out: out = known ? x : V ----------------
// Block: 256 threads, 32 points. Stage V tile [NU][32] (pad 33).
__global__ void k_out(const float* __restrict__ x, float* __restrict__ out) {
    __shared__ float sv[NU*33];
    int pbase = blockIdx.x * 32;
    for (int idx = threadIdx.x; idx < NU*32; idx += 256) {
        int i = idx >> 5, p = idx & 31;
        sv[i*33 + p] = g_VT[(size_t)i*NP + pbase + p];  // coalesced
    }
    __syncthreads();
    for (int idx = threadIdx.x; idx < 32*NN; idx += 256) {
        int p = idx >> 10, n = idx & (NN-1);
        int r = __ldg(&g_rank[n]);
        size_t off = (size_t)(pbase + p)*NN + n;
        float v = (r < 0) ? x[off] : sv[r*33 + p];
        out[off] = v;
    }
}

// ---------------- launch ----------------
extern "C" void kernel_launch(void* const* d_in, const int* in_sizes, int n_in,
                              void* d_out, int out_size) {
    const float* x    = (const float*)d_in[0];
    const float* A    = (const float*)d_in[1];
    const int*   unk  = (const int*)  d_in[2];
    const float* mask = (const float*)d_in[3];
    float* out = (float*)d_out;

    static bool attr_done = false;
    if (!attr_done) {
        cudaFuncSetAttribute(k_rhs,   cudaFuncAttributeMaxDynamicSharedMemorySize, NN*33*4);
        cudaFuncSetAttribute(k_solve, cudaFuncAttributeMaxDynamicSharedMemorySize, NU*128*4);
        attr_done = true;
    }

    k_deg      <<<NN, 256>>>(A);
    k_rank_init<<<4, 256>>>();
    k_rank_set <<<1, 256>>>(unk);
    k_prep     <<<1, 256>>>(A, unk);
    k_rhs      <<<NP/32, 256, NN*33*4>>>(x, mask);
    k_solve    <<<NP/128, 128, NU*128*4>>>();
    k_out      <<<NP/32, 256>>>(x, out);
}

// round 2
// speedup vs baseline: 2.2659x; 2.2659x over previous
#include <cuda_runtime.h>

// Problem constants
#define NB 8
#define NT 4096
#define NN 1024
#define NP (NB*NT)      // 32768 points
#define NU 256          // unknown nodes
#define NKMAX 768
#define PTS 32          // points per block in fused kernel
#define TPB 512         // threads per block in fused kernel
#define NWARP (TPB/32)
#define SXSZ (NN*33)    // floats: x tile transposed [n][33]
#define YSZ  (NU*33)    // floats: y [i][33]

// ---------------- scratch (device globals; allocation-free) ----------------
__device__ float g_deg[NN];
__device__ int   g_rank[NN];          // node -> unknown rank, or -1
__device__ int   g_src[NN];           // smem source offset for output phase
__device__ float g_c[NU];
__device__ float g_invdeg[NU];
__device__ int   g_Kcol[NU*NKMAX];
__device__ int   g_Kcnt[NU];
__device__ int   g_Lcol[NU*NU];
__device__ int   g_Lcnt[NU];
__device__ int   g_order[NU];         // nodes sorted by level
__device__ int   g_lvlptr[NU+1];
__device__ int   g_nlev[1];

// ---------------- k_deg: deg[n] = sum_m A[n,m] ----------------
__global__ void k_deg(const float* __restrict__ A) {
    int n = blockIdx.x;
    float s = 0.f;
    for (int m = threadIdx.x; m < NN; m += 256) s += A[n*NN + m];
    __shared__ float sh[256];
    sh[threadIdx.x] = s; __syncthreads();
    for (int o = 128; o > 0; o >>= 1) {
        if (threadIdx.x < o) sh[threadIdx.x] += sh[threadIdx.x + o];
        __syncthreads();
    }
    if (threadIdx.x == 0) g_deg[n] = sh[0];
}

// ---------------- rank init + scatter + src map ----------------
__global__ void k_rank_init() {
    int t = blockIdx.x*256 + threadIdx.x;
    if (t < NN) g_rank[t] = -1;
}
__global__ void k_rank_set(const int* __restrict__ unk) {
    g_rank[unk[threadIdx.x]] = threadIdx.x;       // 256 threads
}
__global__ void k_src() {
    int n = blockIdx.x*256 + threadIdx.x;
    if (n < NN) {
        int r = g_rank[n];
        g_src[n] = (r < 0) ? n*33 : SXSZ + r*33;
    }
}

// ---------------- k_prep: per-unknown CSR build, 1 warp / unknown ----------
__global__ void k_prep(const float* __restrict__ A, const int* __restrict__ unk) {
    int i = blockIdx.x;                 // 256 blocks, 32 threads each
    int lane = threadIdx.x;
    int ui = unk[i];
    const float* row = A + (size_t)ui * NN;
    unsigned lt = (1u << lane) - 1u;
    int kc = 0, lc = 0; float c = 0.f;
    for (int base = 0; base < NN; base += 32) {
        int n = base + lane;
        float a = row[n];
        int r = g_rank[n];
        bool nz = (a != 0.f);
        unsigned mK = __ballot_sync(0xFFFFFFFFu, nz && r < 0);
        unsigned mL = __ballot_sync(0xFFFFFFFFu, nz && r >= 0 && r < i);
        if (nz) {
            if (r < 0)      g_Kcol[i*NKMAX + kc + __popc(mK & lt)] = n;
            else if (r < i) g_Lcol[i*NU    + lc + __popc(mL & lt)] = r;
            else            c += a;     // r >= i (includes self)
        }
        kc += __popc(mK); lc += __popc(mL);
    }
    // warp reduce c
    for (int o = 16; o > 0; o >>= 1) c += __shfl_down_sync(0xFFFFFFFFu, c, o);
    if (lane == 0) {
        g_Kcnt[i] = kc; g_Lcnt[i] = lc; g_c[i] = c;
        g_invdeg[i] = 1.f / g_deg[ui];
    }
}

// ---------------- k_levels: fixpoint level assignment + counting sort ------
__global__ void k_levels() {
    __shared__ int lev[NU];
    __shared__ int changed;
    int i = threadIdx.x;                 // one block, 256 threads
    lev[i] = 0;
    __syncthreads();
    for (int iter = 0; iter < NU; iter++) {
        if (i == 0) changed = 0;
        __syncthreads();
        int cnt = g_Lcnt[i];
        const int* lc = &g_Lcol[i*NU];
        int nl = 0;
        for (int k = 0; k < cnt; k++) {
            int lj = lev[lc[k]] + 1;
            nl = nl > lj ? nl : lj;
        }
        __syncthreads();
        if (nl != lev[i]) { lev[i] = nl; changed = 1; }
        __syncthreads();
        if (!changed) break;
    }
    // counting sort by level (serial, smem-resident: cheap)
    __shared__ int hist[NU+1];
    if (i == 0) {
        for (int l = 0; l <= NU; l++) hist[l] = 0;
        int maxl = 0;
        for (int n = 0; n < NU; n++) { hist[lev[n]+1]++; if (lev[n] > maxl) maxl = lev[n]; }
        for (int l = 0; l < NU; l++) hist[l+1] += hist[l];
        g_nlev[0] = maxl + 1;
        for (int l = 0; l <= maxl + 1; l++) g_lvlptr[l] = hist[l];
        for (int n = 0; n < NU; n++) g_order[hist[lev[n]]++] = n;
    }
}

// ---------------- fused: load -> gather rhs -> level solve -> write -------
__global__ void __launch_bounds__(TPB, 1) k_fused(const float* __restrict__ x,
                                                  const float* __restrict__ maskp,
                                                  float* __restrict__ out) {
    extern __shared__ float sm[];
    float* sx = sm;            // [NN][33] transposed tile
    float* y  = sm + SXSZ;     // [NU][33]
    __shared__ int s_src[NN];

    int tid = threadIdx.x, lane = tid & 31, w = tid >> 5;
    size_t pbase = (size_t)blockIdx.x * PTS;
    const float* xb = x + pbase * NN;

    for (int n = tid; n < NN; n += TPB) s_src[n] = g_src[n];

    // ---- load + transpose (coalesced LDG.32, conflict-free STS) ----
    #pragma unroll 4
    for (int idx = tid; idx < PTS*NN; idx += TPB) {
        int p = idx >> 10, n = idx & (NN-1);
        sx[n*33 + p] = xb[idx];
    }
    __syncthreads();

    // ---- rhs gather: warp = one unknown, lane = point ----
    float mask = *maskp;
    for (int i = w; i < NU; i += NWARP) {
        int cnt = g_Kcnt[i];
        const int* kc = &g_Kcol[i*NKMAX];
        float acc = 0.f;
        int s = 0;
        #pragma unroll 1
        for (; s + 4 <= cnt; s += 4) {
            int c0 = __ldg(&kc[s]),   c1 = __ldg(&kc[s+1]);
            int c2 = __ldg(&kc[s+2]), c3 = __ldg(&kc[s+3]);
            acc += sx[c0*33+lane] + sx[c1*33+lane]
                 + sx[c2*33+lane] + sx[c3*33+lane];
        }
        for (; s < cnt; s++) acc += sx[__ldg(&kc[s])*33 + lane];
        y[i*33 + lane] = (acc + mask * g_c[i]) * g_invdeg[i];
    }
    __syncthreads();

    // ---- level-scheduled sparse triangular solve ----
    int nlev = g_nlev[0];
    for (int lev = 1; lev < nlev; lev++) {
        int s0 = g_lvlptr[lev], s1 = g_lvlptr[lev+1];
        for (int s = s0 + w; s < s1; s += NWARP) {
            int i = __ldg(&g_order[s]);
            int cnt = g_Lcnt[i];
            const int* lc = &g_Lcol[i*NU];
            float acc = 0.f;
            for (int k = 0; k < cnt; k++)
                acc += y[__ldg(&lc[k])*33 + lane];
            y[i*33 + lane] += acc * g_invdeg[i];
        }
        __syncthreads();
    }

    // ---- write full output tile (select from sx / y via s_src) ----
    float* ob = out + pbase * NN;
    #pragma unroll 4
    for (int idx = tid; idx < PTS*NN; idx += TPB) {
        int p = idx >> 10, n = idx & (NN-1);
        ob[idx] = sm[s_src[n] + p];
    }
}

// ---------------- launch ----------------
extern "C" void kernel_launch(void* const* d_in, const int* in_sizes, int n_in,
                              void* d_out, int out_size) {
    const float* x    = (const float*)d_in[0];
    const float* A    = (const float*)d_in[1];
    const int*   unk  = (const int*)  d_in[2];
    const float* mask = (const float*)d_in[3];
    float* out = (float*)d_out;

    static bool attr_done = false;
    if (!attr_done) {
        cudaFuncSetAttribute(k_fused, cudaFuncAttributeMaxDynamicSharedMemorySize,
                             (SXSZ + YSZ) * 4);
        attr_done = true;
    }

    k_deg      <<<NN, 256>>>(A);
    k_rank_init<<<4, 256>>>();
    k_rank_set <<<1, 256>>>(unk);
    k_src      <<<4, 256>>>();
    k_prep     <<<NU, 32>>>(A, unk);
    k_levels   <<<1, 256>>>();
    k_fused    <<<NP/PTS, TPB, (SXSZ + YSZ)*4>>>(x, mask, out);
}

// round 3
// speedup vs baseline: 3.5951x; 1.5866x over previous
#include <cuda_runtime.h>

// Problem constants
#define NB 8
#define NT 4096
#define NN 1024
#define NP (NB*NT)      // 32768 points
#define NU 256          // unknown nodes
#define NKMAX 768
#define PTS 32          // points per fused block
#define TPB 1024
#define SALL ((NN+NU)*33)   // sx tile [1024][33] + y [256][33], one address space
#define KCAP 9216           // compact known-CSR capacity (mean ~5900, +44 sd)
#define LCAP 2048           // compact lower-CSR capacity (mean ~980, +34 sd)

// ---------------- scratch (device globals; allocation-free) ----------------
__device__ float g_invdeg[NU];
__device__ float g_c[NU];
__device__ int   g_rank[NN];
__device__ int   g_Kcol[NU*NKMAX];   // padded known-neighbor node ids
__device__ int   g_Kcnt[NU];
__device__ int   g_Lcol[NU*NU];      // padded earlier-unknown ranks
__device__ int   g_Lcnt[NU];
__device__ int   g_Kc[KCAP];         // compact: node*33
__device__ int   g_Lc[LCAP];         // compact: (NN+rank)*33
__device__ int   g_Kptr[NU+1];
__device__ int   g_Lptr[NU+1];
__device__ int   g_Ktot, g_Ltot;
__device__ float g_rhsc[NU];         // mask*c*invdeg
__device__ int   g_uoff[NU];         // unk[i]*33
__device__ int   g_order[NU];
__device__ int   g_lvlptr[NU+1];
__device__ int   g_nlev[1];

// ---------------- 0: rank init + set (one block) ----------------
__global__ void k_rank(const int* __restrict__ unk) {
    int t = threadIdx.x;                // 1024 threads
    g_rank[t] = -1;
    __syncthreads();
    if (t < NU) g_rank[unk[t]] = t;
}

// ---------------- 1: invdeg for unknown rows only ----------------
__global__ void k_deg_u(const float* __restrict__ A, const int* __restrict__ unk) {
    int i = blockIdx.x;                 // 256 blocks x 256 threads
    int ui = unk[i];
    float s = 0.f;
    for (int m = threadIdx.x; m < NN; m += 256) s += A[(size_t)ui*NN + m];
    __shared__ float sh[256];
    sh[threadIdx.x] = s; __syncthreads();
    for (int o = 128; o > 0; o >>= 1) {
        if (threadIdx.x < o) sh[threadIdx.x] += sh[threadIdx.x + o];
        __syncthreads();
    }
    if (threadIdx.x == 0) g_invdeg[i] = 1.f / sh[0];
}

// ---------------- 2: padded CSR build, 1 warp / unknown ----------------
__global__ void k_prep(const float* __restrict__ A, const int* __restrict__ unk) {
    int i = blockIdx.x;                 // 256 blocks, 32 threads
    int lane = threadIdx.x;
    int ui = unk[i];
    const float* row = A + (size_t)ui * NN;
    unsigned lt = (1u << lane) - 1u;
    int kc = 0, lc = 0; float c = 0.f;
    for (int base = 0; base < NN; base += 32) {
        int n = base + lane;
        float a = row[n];
        int r = g_rank[n];
        bool nz = (a != 0.f);
        unsigned mK = __ballot_sync(0xFFFFFFFFu, nz && r < 0);
        unsigned mL = __ballot_sync(0xFFFFFFFFu, nz && r >= 0 && r < i);
        if (nz) {
            if (r < 0)      g_Kcol[i*NKMAX + kc + __popc(mK & lt)] = n;
            else if (r < i) g_Lcol[i*NU    + lc + __popc(mL & lt)] = r;
            else            c += a;     // r >= i (includes self)
        }
        kc += __popc(mK); lc += __popc(mL);
    }
    for (int o = 16; o > 0; o >>= 1) c += __shfl_down_sync(0xFFFFFFFFu, c, o);
    if (lane == 0) { g_Kcnt[i] = kc; g_Lcnt[i] = lc; g_c[i] = c; }
}

// ---------------- 3: compact CSR + rhs constants (one block) ----------------
__global__ void k_compact(const int* __restrict__ unk, const float* __restrict__ maskp) {
    __shared__ int kptr[NU+1], lptr[NU+1];
    int t = threadIdx.x;                // 1024 threads
    if (t == 0) {
        int ka = 0, la = 0;
        for (int i = 0; i < NU; i++) {
            kptr[i] = ka; ka += g_Kcnt[i];
            lptr[i] = la; la += g_Lcnt[i];
        }
        kptr[NU] = ka; lptr[NU] = la;
        g_Ktot = ka < KCAP ? ka : KCAP;
        g_Ltot = la < LCAP ? la : LCAP;
    }
    __syncthreads();
    int w = t >> 5, lane = t & 31;
    for (int i = w; i < NU; i += 32) {
        int b = kptr[i], c = g_Kcnt[i];
        for (int s = lane; s < c; s += 32)
            if (b + s < KCAP) g_Kc[b + s] = g_Kcol[i*NKMAX + s] * 33;
        b = lptr[i]; c = g_Lcnt[i];
        for (int s = lane; s < c; s += 32)
            if (b + s < LCAP) g_Lc[b + s] = (NN + g_Lcol[i*NU + s]) * 33;
    }
    if (t <= NU) { g_Kptr[t] = kptr[t]; g_Lptr[t] = lptr[t]; }
    if (t < NU) {
        g_uoff[t] = unk[t] * 33;
        g_rhsc[t] = maskp[0] * g_c[t] * g_invdeg[t];
    }
}

// ---------------- 4: level assignment + counting sort (one block) ----------
__global__ void k_levels() {
    __shared__ int lev[NU];
    __shared__ int changed;
    int i = threadIdx.x;                 // 256 threads
    lev[i] = 0;
    __syncthreads();
    for (int iter = 0; iter < NU; iter++) {
        if (i == 0) changed = 0;
        __syncthreads();
        int cnt = g_Lcnt[i];
        const int* lc = &g_Lcol[i*NU];
        int nl = 0;
        for (int k = 0; k < cnt; k++) {
            int lj = lev[lc[k]] + 1;
            nl = nl > lj ? nl : lj;
        }
        __syncthreads();
        if (nl != lev[i]) { lev[i] = nl; changed = 1; }
        __syncthreads();
        if (!changed) break;
    }
    __shared__ int hist[NU+1];
    if (i == 0) {
        for (int l = 0; l <= NU; l++) hist[l] = 0;
        int maxl = 0;
        for (int n = 0; n < NU; n++) { hist[lev[n]+1]++; if (lev[n] > maxl) maxl = lev[n]; }
        for (int l = 0; l < NU; l++) hist[l+1] += hist[l];
        g_nlev[0] = maxl + 1;
        for (int l = 0; l <= maxl + 1; l++) g_lvlptr[l] = hist[l];
        for (int n = 0; n < NU; n++) g_order[hist[lev[n]]++] = n;
    }
}

// ---------------- 5: fused load -> gather -> solve -> scatter -> copy ------
__global__ void __launch_bounds__(TPB, 1) k_fused(const float* __restrict__ x,
                                                  float* __restrict__ out) {
    extern __shared__ float sm[];
    float* sx   = sm;                         // [(NN+NU)][33]
    int*  sKoff = (int*)(sm + SALL);          // KCAP
    int*  sLoff = sKoff + KCAP;               // LCAP
    int*  sKptr = sLoff + LCAP;               // NU+1
    int*  sLptr = sKptr + (NU+1);             // NU+1
    int*  sOrd  = sLptr + (NU+1);             // NU
    int*  sLvl  = sOrd + NU;                  // NU+1
    float* sInv = (float*)(sLvl + (NU+1));    // NU
    float* sRhs = sInv + NU;                  // NU
    int*  sUoff = (int*)(sRhs + NU);          // NU
    __shared__ int s_nlev;

    int tid = threadIdx.x, lane = tid & 31, w = tid >> 5;
    const float* xb = x   + (size_t)blockIdx.x * PTS * NN;
    float*       ob = out + (size_t)blockIdx.x * PTS * NN;

    // ---- stage metadata ----
    int ktot = g_Ktot, ltot = g_Ltot;
    for (int s = tid; s < ktot; s += TPB) sKoff[s] = g_Kc[s];
    for (int s = tid; s < ltot; s += TPB) sLoff[s] = g_Lc[s];
    if (tid <= NU) { sKptr[tid] = g_Kptr[tid]; sLptr[tid] = g_Lptr[tid]; sLvl[tid] = g_lvlptr[tid]; }
    if (tid < NU)  { sOrd[tid] = g_order[tid]; sInv[tid] = g_invdeg[tid];
                     sRhs[tid] = g_rhsc[tid];  sUoff[tid] = g_uoff[tid]; }
    if (tid == 0) s_nlev = g_nlev[0];

    // ---- load x tile: thread = column n=tid, 32 points, 8-deep batches ----
    #pragma unroll
    for (int b = 0; b < PTS/8; b++) {
        float r[8];
        #pragma unroll
        for (int j = 0; j < 8; j++) r[j] = xb[(size_t)(b*8 + j)*NN + tid];
        #pragma unroll
        for (int j = 0; j < 8; j++) sx[tid*33 + b*8 + j] = r[j];
    }
    __syncthreads();

    // ---- rhs gather: warp = unknown, lane = point, smem-only inner loop ----
    #pragma unroll 1
    for (int ii = 0; ii < NU/32; ii++) {
        int i = (w << 3) + ii;
        int s = sKptr[i], e = sKptr[i+1];
        float a0 = 0.f, a1 = 0.f;
        #pragma unroll 1
        for (; s + 4 <= e; s += 4) {
            int o0 = sKoff[s], o1 = sKoff[s+1], o2 = sKoff[s+2], o3 = sKoff[s+3];
            a0 += sx[o0 + lane]; a1 += sx[o1 + lane];
            a0 += sx[o2 + lane]; a1 += sx[o3 + lane];
        }
        for (; s < e; s++) a0 += sx[sKoff[s] + lane];
        sx[(NN + i)*33 + lane] = (a0 + a1) * sInv[i] + sRhs[i];
    }
    __syncthreads();

    // ---- level-scheduled sparse triangular solve (in smem) ----
    int nlev = s_nlev;
    for (int lev = 1; lev < nlev; lev++) {
        for (int s = sLvl[lev] + w; s < sLvl[lev+1]; s += 32) {
            int i = sOrd[s];
            int a = sLptr[i], e = sLptr[i+1];
            float acc = 0.f;
            for (; a < e; a++) acc += sx[sLoff[a] + lane];
            sx[(NN + i)*33 + lane] += acc * sInv[i];
        }
        __syncthreads();
    }

    // ---- scatter solved values into their x-tile columns ----
    for (int i = w; i < NU; i += 32)
        sx[sUoff[i] + lane] = sx[(NN + i)*33 + lane];
    __syncthreads();

    // ---- pure copy out (branchless, conflict-free, coalesced) ----
    #pragma unroll
    for (int b = 0; b < PTS/8; b++) {
        float r[8];
        #pragma unroll
        for (int j = 0; j < 8; j++) r[j] = sx[tid*33 + b*8 + j];
        #pragma unroll
        for (int j = 0; j < 8; j++) ob[(size_t)(b*8 + j)*NN + tid] = r[j];
    }
}

// ---------------- launch ----------------
extern "C" void kernel_launch(void* const* d_in, const int* in_sizes, int n_in,
                              void* d_out, int out_size) {
    const float* x    = (const float*)d_in[0];
    const float* A    = (const float*)d_in[1];
    const int*   unk  = (const int*)  d_in[2];
    const float* mask = (const float*)d_in[3];
    float* out = (float*)d_out;

    const int SMEM = SALL*4 + KCAP*4 + LCAP*4 + (NU+1)*4*3 + NU*4*4;

    static bool attr_done = false;
    if (!attr_done) {
        cudaFuncSetAttribute(k_fused, cudaFuncAttributeMaxDynamicSharedMemorySize, SMEM);
        attr_done = true;
    }

    k_rank    <<<1, TPB>>>(unk);
    k_deg_u   <<<NU, 256>>>(A, unk);
    k_prep    <<<NU, 32>>>(A, unk);
    k_compact <<<1, TPB>>>(unk, mask);
    k_levels  <<<1, NU>>>();
    k_fused   <<<NP/PTS, TPB, SMEM>>>(x, out);
}

// round 4
// speedup vs baseline: 3.9191x; 1.0901x over previous
#include <cuda_runtime.h>

// Problem constants
#define NB 8
#define NT 4096
#define NN 1024
#define NP (NB*NT)      // 32768 points
#define NU 256          // unknown nodes
#define NKMAX 768
#define PTS 32          // points per fused block
#define TPB 1024
#define SROW 33         // smem stride of transposed tile column
#define SXSZ (NN*SROW)  // 33792 floats
#define KCAP 9216       // compact known-CSR cap (mean ~5900, >40 sd margin)
#define LCAP 2048       // compact lower-CSR cap (mean ~980, >30 sd margin)

typedef unsigned short u16;
typedef unsigned int   u32;

// ---------------- scratch (device globals; allocation-free) ----------------
__device__ float g_invdeg[NU];
__device__ float g_c[NU];
__device__ int   g_rank[NN];
__device__ int   g_Kcol[NU*NKMAX];   // padded known-neighbor node ids
__device__ int   g_Kcnt[NU];
__device__ int   g_Lcol[NU*NU];      // padded earlier-unknown ranks
__device__ int   g_Lcnt[NU];
__device__ u16   g_Kc[KCAP];         // compact: node*33 (u16)
__device__ u16   g_Lc[LCAP];         // compact: unk[rank]*33 (u16)
__device__ int   g_Kptr[NU+1];
__device__ int   g_Lptr[NU+1];
__device__ int   g_Ktot, g_Ltot;
__device__ float g_rhsc[NU];         // mask*c*invdeg
__device__ int   g_woff[NU];         // unk[i]*33 (tile write offset)
__device__ int   g_order[NU];
__device__ int   g_lvlptr[NU+1];
__device__ int   g_nlev[1];

// ---------------- launch 0: rank map ----------------
__global__ void k_rank(const int* __restrict__ unk) {
    int t = threadIdx.x;                // 1024 threads
    g_rank[t] = -1;
    __syncthreads();
    if (t < NU) g_rank[unk[t]] = t;
}

// ---------------- launch 1: per-row pass: deg + padded CSR + c ------------
__global__ void k_row(const float* __restrict__ A, const int* __restrict__ unk) {
    int i = blockIdx.x;                 // 256 blocks, 1 warp each
    int lane = threadIdx.x;
    int ui = unk[i];
    const float* row = A + (size_t)ui * NN;
    unsigned lt = (1u << lane) - 1u;
    int kc = 0, lc = 0; float c = 0.f, d = 0.f;
    for (int base = 0; base < NN; base += 32) {
        int n = base + lane;
        float a = row[n];
        int r = g_rank[n];
        bool nz = (a != 0.f);
        d += a;
        unsigned mK = __ballot_sync(0xFFFFFFFFu, nz && r < 0);
        unsigned mL = __ballot_sync(0xFFFFFFFFu, nz && r >= 0 && r < i);
        if (nz) {
            if (r < 0)      g_Kcol[i*NKMAX + kc + __popc(mK & lt)] = n;
            else if (r < i) g_Lcol[i*NU    + lc + __popc(mL & lt)] = r;
            else            c += a;     // r >= i (includes self)
        }
        kc += __popc(mK); lc += __popc(mL);
    }
    for (int o = 16; o > 0; o >>= 1) {
        c += __shfl_down_sync(0xFFFFFFFFu, c, o);
        d += __shfl_down_sync(0xFFFFFFFFu, d, o);
    }
    if (lane == 0) {
        g_Kcnt[i] = kc; g_Lcnt[i] = lc; g_c[i] = c;
        g_invdeg[i] = 1.f / d;
    }
}

// ---------------- launch 2: compact + constants + levels (one block) -------
__global__ void k_meta(const int* __restrict__ unk, const float* __restrict__ maskp) {
    __shared__ int skcnt[NU], slcnt[NU], kptr[NU+1], lptr[NU+1];
    __shared__ int sunk[NU];
    __shared__ u16 sLrank[LCAP];
    __shared__ int lev[NU], hist[NU+1];
    __shared__ int changed;
    int t = threadIdx.x;                // 1024 threads
    if (t < NU) {
        skcnt[t] = g_Kcnt[t]; slcnt[t] = g_Lcnt[t]; sunk[t] = unk[t];
    }
    __syncthreads();
    if (t == 0) {                       // serial scan over smem: cheap
        int ka = 0, la = 0;
        for (int i = 0; i < NU; i++) {
            kptr[i] = ka; ka += skcnt[i];
            lptr[i] = la; la += slcnt[i];
        }
        kptr[NU] = ka; lptr[NU] = la;
        g_Ktot = ka < KCAP ? ka : KCAP;
        g_Ltot = la < LCAP ? la : LCAP;
    }
    __syncthreads();
    int w = t >> 5, lane = t & 31;
    for (int i = w; i < NU; i += 32) {
        int b = kptr[i], c = skcnt[i];
        for (int s = lane; s < c; s += 32)
            if (b + s < KCAP) g_Kc[b + s] = (u16)(g_Kcol[i*NKMAX + s] * SROW);
        b = lptr[i]; c = slcnt[i];
        for (int s = lane; s < c; s += 32)
            if (b + s < LCAP) {
                int r = g_Lcol[i*NU + s];
                g_Lc[b + s]    = (u16)(sunk[r] * SROW);
                sLrank[b + s]  = (u16)r;
            }
    }
    if (t <= NU) { g_Kptr[t] = kptr[t]; g_Lptr[t] = lptr[t]; }
    if (t < NU) {
        g_woff[t] = sunk[t] * SROW;
        g_rhsc[t] = maskp[0] * g_c[t] * g_invdeg[t];
    }
    __syncthreads();
    // ---- level fixpoint on smem-staged lists ----
    if (t < NU) lev[t] = 0;
    __syncthreads();
    for (int iter = 0; iter < NU; iter++) {
        if (t == 0) changed = 0;
        __syncthreads();
        int nl = 0;
        if (t < NU) {
            for (int s = lptr[t]; s < lptr[t+1] && s < LCAP; s++) {
                int lj = lev[sLrank[s]] + 1;
                nl = nl > lj ? nl : lj;
            }
        }
        __syncthreads();
        if (t < NU && nl != lev[t]) { lev[t] = nl; changed = 1; }
        __syncthreads();
        if (!changed) break;
    }
    if (t == 0) {                       // counting sort (smem, serial, cheap)
        for (int l = 0; l <= NU; l++) hist[l] = 0;
        int maxl = 0;
        for (int n = 0; n < NU; n++) { hist[lev[n]+1]++; if (lev[n] > maxl) maxl = lev[n]; }
        for (int l = 0; l < NU; l++) hist[l+1] += hist[l];
        g_nlev[0] = maxl + 1;
        for (int l = 0; l <= maxl + 1; l++) g_lvlptr[l] = hist[l];
        for (int n = 0; n < NU; n++) g_order[hist[lev[n]]++] = n;
    }
}

// ---------------- launch 3: fused load -> gather -> solve -> copy ----------
__global__ void __launch_bounds__(TPB, 1) k_fused(const float* __restrict__ x,
                                                  float* __restrict__ out) {
    extern __shared__ float sm[];
    float* sx    = sm;                          // [NN][33], unknowns solved in place
    u16*   sKoff = (u16*)(sm + SXSZ);           // KCAP
    u16*   sLoff = sKoff + KCAP;                // LCAP
    int*   sKptr = (int*)(sLoff + LCAP);        // NU+1
    int*   sLptr = sKptr + (NU+1);              // NU+1
    int*   sOrd  = sLptr + (NU+1);              // NU
    int*   sLvl  = sOrd + NU;                   // NU+1
    float* sInv  = (float*)(sLvl + (NU+1));     // NU
    float* sRhs  = sInv + NU;                   // NU
    int*   sWoff = (int*)(sRhs + NU);           // NU
    __shared__ int s_nlev;

    int tid = threadIdx.x, lane = tid & 31, w = tid >> 5;
    const float* xb = x   + (size_t)blockIdx.x * PTS * NN;
    float*       ob = out + (size_t)blockIdx.x * PTS * NN;

    // ---- stage metadata (u16 arrays moved as u32 pairs) ----
    int ktot = g_Ktot, ltot = g_Ltot;
    const u32* gk = (const u32*)g_Kc;  u32* sk = (u32*)sKoff;
    const u32* gl = (const u32*)g_Lc;  u32* sl = (u32*)sLoff;
    for (int s = tid; s < (ktot+1)/2; s += TPB) sk[s] = gk[s];
    for (int s = tid; s < (ltot+1)/2; s += TPB) sl[s] = gl[s];
    if (tid <= NU) { sKptr[tid] = g_Kptr[tid]; sLptr[tid] = g_Lptr[tid]; sLvl[tid] = g_lvlptr[tid]; }
    if (tid < NU)  { sOrd[tid] = g_order[tid]; sInv[tid] = g_invdeg[tid];
                     sRhs[tid] = g_rhsc[tid];  sWoff[tid] = g_woff[tid]; }
    if (tid == 0) s_nlev = g_nlev[0];

    // ---- load x tile transposed: thread = column n=tid ----
    #pragma unroll
    for (int b = 0; b < PTS/8; b++) {
        float r[8];
        #pragma unroll
        for (int j = 0; j < 8; j++) r[j] = xb[(size_t)(b*8 + j)*NN + tid];
        #pragma unroll
        for (int j = 0; j < 8; j++) sx[tid*SROW + b*8 + j] = r[j];
    }
    __syncthreads();

    // ---- rhs gather: warp = unknown, lane = point ----
    const float* sxl = sx + lane;
    #pragma unroll 1
    for (int ii = 0; ii < NU/32; ii++) {
        int i = (w << 3) + ii;
        int s = sKptr[i], e = sKptr[i+1];
        float a0 = 0.f, a1 = 0.f;
        if ((s & 1) && s < e) { a0 += sxl[sKoff[s]]; s++; }
        int np = (e - s) >> 1;
        const u32* ip = (const u32*)(sKoff + s);
        #pragma unroll 4
        for (int q = 0; q < np; q++) {
            u32 pk = ip[q];
            a0 += sxl[pk & 0xFFFFu];
            a1 += sxl[pk >> 16];
        }
        if ((e - s) & 1) a0 += sxl[sKoff[e-1]];
        sx[sWoff[i] + lane] = (a0 + a1) * sInv[i] + sRhs[i];
    }
    __syncthreads();

    // ---- level-scheduled solve, in place in the tile ----
    int nlev = s_nlev;
    for (int lev = 1; lev < nlev; lev++) {
        for (int s = sLvl[lev] + w; s < sLvl[lev+1]; s += 32) {
            int i = sOrd[s];
            int a = sLptr[i], e = sLptr[i+1];
            float acc = 0.f;
            for (; a < e; a++) acc += sxl[sLoff[a]];
            sx[sWoff[i] + lane] += acc * sInv[i];
        }
        __syncthreads();
    }

    // ---- pure copy out (tile already holds final values) ----
    #pragma unroll
    for (int b = 0; b < PTS/8; b++) {
        float r[8];
        #pragma unroll
        for (int j = 0; j < 8; j++) r[j] = sx[tid*SROW + b*8 + j];
        #pragma unroll
        for (int j = 0; j < 8; j++) ob[(size_t)(b*8 + j)*NN + tid] = r[j];
    }
}

// ---------------- launch ----------------
extern "C" void kernel_launch(void* const* d_in, const int* in_sizes, int n_in,
                              void* d_out, int out_size) {
    const float* x    = (const float*)d_in[0];
    const float* A    = (const float*)d_in[1];
    const int*   unk  = (const int*)  d_in[2];
    const float* mask = (const float*)d_in[3];
    float* out = (float*)d_out;

    const int SMEM = SXSZ*4 + KCAP*2 + LCAP*2
                   + (NU+1)*4*3 + NU*4*4 + 64;

    static bool attr_done = false;
    if (!attr_done) {
        cudaFuncSetAttribute(k_fused, cudaFuncAttributeMaxDynamicSharedMemorySize, SMEM);
        attr_done = true;
    }

    k_rank  <<<1, TPB>>>(unk);        // launch 0
    k_row   <<<NU, 32>>>(A, unk);     // launch 1
    k_meta  <<<1, TPB>>>(unk, mask);  // launch 2
    k_fused <<<NP/PTS, TPB, SMEM>>>(x, out);  // launch 3  (ncu lands here)
}

// round 5
// speedup vs baseline: 4.6104x; 1.1764x over previous
#include <cuda_runtime.h>

// Problem constants
#define NB 8
#define NT 4096
#define NN 1024
#define NP (NB*NT)      // 32768 points
#define NU 256          // unknown nodes
#define NKMAX 768
#define PTS 32          // points per fused block
#define TPB 1024
#define SROW2 17        // float2 stride per column (32 pts = 16 float2 + 1 pad)
#define DUMMY (NN*SROW2)   // float2-index of zeroed dummy column (17408, fits u16)
#define KCAP 12288      // compact known-CSR cap (u16), pair-padded
#define LCAP 3072       // compact lower-CSR cap (u16), padded to 4

typedef unsigned short u16;
typedef unsigned int   u32;
typedef unsigned long long ull;

__device__ __forceinline__ void fadd2(ull& a, ull b) {
    asm("add.rn.f32x2 %0, %0, %1;" : "+l"(a) : "l"(b));
}

// ---------------- scratch (device globals; allocation-free) ----------------
__device__ float g_invdeg[NU];
__device__ float g_c[NU];
__device__ int   g_rank[NN];
__device__ int   g_Kcol[NU*NKMAX];
__device__ int   g_Kcnt[NU];
__device__ int   g_Lcol[NU*NU];
__device__ int   g_Lcnt[NU];
__device__ u16   g_Kc[KCAP];      // col*17, dummy-padded
__device__ u16   g_Lc[LCAP];      // unk[rank]*17, dummy-padded
__device__ int   g_Kptr[NU];
__device__ int   g_Nit[NU/2];     // gather iterations (of 4 elems) per pair
__device__ int   g_Lptr[NU+1];
__device__ int   g_Ktot, g_Ltot;
__device__ float g_rhsc[NU];
__device__ int   g_woff[NU];      // unk[i]*17
__device__ int   g_order[NU];
__device__ int   g_lvlptr[NU+1];
__device__ int   g_nlev[1];

// ---------------- launch 0: rank map ----------------
__global__ void k_rank(const int* __restrict__ unk) {
    int t = threadIdx.x;
    g_rank[t] = -1;
    __syncthreads();
    if (t < NU) g_rank[unk[t]] = t;
}

// ---------------- launch 1: per-row: deg + padded CSR + c ------------------
__global__ void k_row(const float* __restrict__ A, const int* __restrict__ unk) {
    int i = blockIdx.x;                 // 256 blocks, 1 warp
    int lane = threadIdx.x;
    int ui = unk[i];
    const float* row = A + (size_t)ui * NN;
    unsigned lt = (1u << lane) - 1u;
    int kc = 0, lc = 0; float c = 0.f, d = 0.f;
    for (int base = 0; base < NN; base += 32) {
        int n = base + lane;
        float a = row[n];
        int r = g_rank[n];
        bool nz = (a != 0.f);
        d += a;
        unsigned mK = __ballot_sync(0xFFFFFFFFu, nz && r < 0);
        unsigned mL = __ballot_sync(0xFFFFFFFFu, nz && r >= 0 && r < i);
        if (nz) {
            if (r < 0)      g_Kcol[i*NKMAX + kc + __popc(mK & lt)] = n;
            else if (r < i) g_Lcol[i*NU    + lc + __popc(mL & lt)] = r;
            else            c += a;     // r >= i (includes self)
        }
        kc += __popc(mK); lc += __popc(mL);
    }
    for (int o = 16; o > 0; o >>= 1) {
        c += __shfl_down_sync(0xFFFFFFFFu, c, o);
        d += __shfl_down_sync(0xFFFFFFFFu, d, o);
    }
    if (lane == 0) {
        g_Kcnt[i] = kc; g_Lcnt[i] = lc; g_c[i] = c;
        g_invdeg[i] = 1.f / d;
    }
}

// ---------------- launch 2: compact + constants + levels (parallel) --------
__global__ void k_meta(const int* __restrict__ unk, const float* __restrict__ maskp) {
    __shared__ int skcnt[NU], slcnt[NU], sunk[NU];
    __shared__ int pairLen[NU/2], scanA[NU], lp4[NU];
    __shared__ int kptr[NU], lptr[NU+1];
    __shared__ u16 slrank[LCAP];
    __shared__ int lev[NU];
    __shared__ int changed, smax;
    int t = threadIdx.x;                // 1024 threads
    if (t < NU) { skcnt[t] = g_Kcnt[t]; slcnt[t] = g_Lcnt[t]; sunk[t] = unk[t]; }
    __syncthreads();
    if (t < NU/2) {
        int m = skcnt[2*t] > skcnt[2*t+1] ? skcnt[2*t] : skcnt[2*t+1];
        pairLen[t] = (m + 3) & ~3;
    }
    if (t < NU) lp4[t] = (slcnt[t] + 3) & ~3;
    __syncthreads();
    // inclusive scan of pairLen (n=128) into scanA
    if (t < NU/2) scanA[t] = pairLen[t];
    __syncthreads();
    for (int off = 1; off < NU/2; off <<= 1) {
        int v = (t < NU/2 && t >= off) ? scanA[t-off] : 0;
        __syncthreads();
        if (t < NU/2) scanA[t] += v;
        __syncthreads();
    }
    if (t < NU) {
        int j = t >> 1;
        kptr[t] = 2*(scanA[j] - pairLen[j]) + (t & 1)*pairLen[j];
    }
    if (t == 0) g_Ktot = 2*scanA[NU/2-1] < KCAP ? 2*scanA[NU/2-1] : KCAP;
    __syncthreads();
    // inclusive scan of lp4 (n=256) into scanA (reuse)
    if (t < NU) scanA[t] = lp4[t];
    __syncthreads();
    for (int off = 1; off < NU; off <<= 1) {
        int v = (t < NU && t >= off) ? scanA[t-off] : 0;
        __syncthreads();
        if (t < NU) scanA[t] += v;
        __syncthreads();
    }
    if (t < NU) lptr[t] = scanA[t] - lp4[t];
    if (t == 0) {
        lptr[NU] = scanA[NU-1];
        g_Ltot = scanA[NU-1] < LCAP ? scanA[NU-1] : LCAP;
    }
    __syncthreads();
    // compaction: warp per unknown (32 warps x 8)
    int w = t >> 5, lane = t & 31;
    for (int ii = 0; ii < 8; ii++) {
        int i = w + 32*ii;
        int kb = kptr[i], kc = skcnt[i], kp = pairLen[i >> 1];
        for (int s = lane; s < kp; s += 32) {
            u16 v = (s < kc) ? (u16)(g_Kcol[i*NKMAX + s] * SROW2) : (u16)DUMMY;
            if (kb + s < KCAP) g_Kc[kb + s] = v;
        }
        int lb = lptr[i], lc = slcnt[i], lp = lp4[i];
        for (int s = lane; s < lp; s += 32) {
            u16 v = (u16)DUMMY;
            if (s < lc) {
                int r = g_Lcol[i*NU + s];
                v = (u16)(sunk[r] * SROW2);
                if (lb + s < LCAP) slrank[lb + s] = (u16)r;
            }
            if (lb + s < LCAP) g_Lc[lb + s] = v;
        }
    }
    if (t < NU) {
        g_rhsc[t] = maskp[0] * g_c[t] * g_invdeg[t];
        g_woff[t] = sunk[t] * SROW2;
        g_Kptr[t] = kptr[t];
    }
    if (t < NU/2) g_Nit[t] = pairLen[t] >> 2;
    if (t <= NU) g_Lptr[t] = lptr[t];
    __syncthreads();
    // ---- level fixpoint on smem-staged ranks ----
    if (t < NU) lev[t] = 0;
    __syncthreads();
    for (int iter = 0; iter < NU; iter++) {
        if (t == 0) changed = 0;
        __syncthreads();
        int nl = 0;
        if (t < NU) {
            int b = lptr[t], e = b + slcnt[t];
            if (e > LCAP) e = LCAP;
            for (int s = b; s < e; s++) {
                int lj = lev[slrank[s]] + 1;
                nl = nl > lj ? nl : lj;
            }
        }
        __syncthreads();
        if (t < NU && nl != lev[t]) { lev[t] = nl; changed = 1; }
        __syncthreads();
        if (!changed) break;
    }
    if (t == 0) smax = 0;
    __syncthreads();
    if (t < NU) atomicMax(&smax, lev[t]);
    __syncthreads();
    if (t <= NU) {          // lvlptr[l] = #{j : lev[j] < l}
        int c = 0;
        for (int j = 0; j < NU; j++) c += (lev[j] < t);
        g_lvlptr[t] = c;
    }
    if (t < NU) {           // stable sort position
        int my = lev[t], pos = 0;
        for (int j = 0; j < NU; j++) {
            int lj = lev[j];
            pos += (lj < my) || (lj == my && j < t);
        }
        g_order[pos] = t;
    }
    if (t == 0) g_nlev[0] = smax + 1;
}

// ---------------- launch 3: fused load -> gather -> solve -> copy ----------
__global__ void __launch_bounds__(TPB, 1) k_fused(const float* __restrict__ x,
                                                  float* __restrict__ out) {
    extern __shared__ char smraw[];
    float2* sx2   = (float2*)smraw;                          // (NN+1)*17 float2
    char* p = smraw + (NN+1)*SROW2*sizeof(float2);
    int*   sKptr = (int*)p;          p += NU*4;
    int*   sNit  = (int*)p;          p += (NU/2)*4;
    int*   sLptr = (int*)p;          p += (NU+1)*4;
    int*   sOrd  = (int*)p;          p += NU*4;
    int*   sLvl  = (int*)p;          p += (NU+1)*4;
    float* sInv  = (float*)p;        p += NU*4;
    float* sRhs  = (float*)p;        p += NU*4;
    int*   sWoff = (int*)p;          p += NU*4;
    u16*   sKoff = (u16*)p;          p += KCAP*2;
    u16*   sLoff = (u16*)p;
    __shared__ int s_nlev;

    int tid = threadIdx.x, lane = tid & 31, w = tid >> 5;
    int h2 = lane >> 4, pl = lane & 15;
    const float* xb = x   + (size_t)blockIdx.x * PTS * NN;
    float*       ob = out + (size_t)blockIdx.x * PTS * NN;

    // ---- stage metadata ----
    int ktot = g_Ktot, ltot = g_Ltot;
    {
        u32* dk = (u32*)sKoff; const u32* gk = (const u32*)g_Kc;
        for (int s = tid; s < (ktot >> 1); s += TPB) dk[s] = gk[s];
        u32* dl = (u32*)sLoff; const u32* gl = (const u32*)g_Lc;
        for (int s = tid; s < (ltot >> 1); s += TPB) dl[s] = gl[s];
    }
    if (tid < NU) { sKptr[tid] = g_Kptr[tid]; sOrd[tid] = g_order[tid];
                    sInv[tid] = g_invdeg[tid]; sRhs[tid] = g_rhsc[tid];
                    sWoff[tid] = g_woff[tid]; }
    if (tid < NU/2) sNit[tid] = g_Nit[tid];
    if (tid <= NU) { sLptr[tid] = g_Lptr[tid]; sLvl[tid] = g_lvlptr[tid]; }
    if (tid == 0) s_nlev = g_nlev[0];

    // ---- load x tile: thread = column n=tid, points packed as float2 ----
    {
        float v[16];
        #pragma unroll
        for (int q = 0; q < 16; q++) v[q] = xb[(size_t)q*NN + tid];
        #pragma unroll
        for (int q = 0; q < 8; q++) sx2[tid*SROW2 + q] = make_float2(v[2*q], v[2*q+1]);
        #pragma unroll
        for (int q = 0; q < 16; q++) v[q] = xb[(size_t)(16+q)*NN + tid];
        #pragma unroll
        for (int q = 0; q < 8; q++) sx2[tid*SROW2 + 8 + q] = make_float2(v[2*q], v[2*q+1]);
    }
    if (tid < SROW2) sx2[DUMMY + tid] = make_float2(0.f, 0.f);  // zero dummy col
    __syncthreads();

    const ull* sxp = ((const ull*)sx2) + pl;

    // ---- rhs gather: half-warp = one unknown, 16 lanes x float2 = 32 pts ----
    #pragma unroll 1
    for (int ii = 0; ii < 4; ii++) {
        int j = (w << 2) + ii;           // pair 0..127
        int i = (j << 1) + h2;           // unknown 0..255
        const uint2* ip = (const uint2*)(sKoff + sKptr[i]);
        int nIt = sNit[j];
        ull a0 = 0, a1 = 0, a2 = 0, a3 = 0;
        #pragma unroll 2
        for (int q = 0; q < nIt; q++) {
            uint2 pk = ip[q];
            fadd2(a0, sxp[pk.x & 0xFFFFu]);
            fadd2(a1, sxp[pk.x >> 16]);
            fadd2(a2, sxp[pk.y & 0xFFFFu]);
            fadd2(a3, sxp[pk.y >> 16]);
        }
        fadd2(a0, a1); fadd2(a2, a3); fadd2(a0, a2);
        float tx, ty;
        asm("mov.b64 {%0, %1}, %2;" : "=f"(tx), "=f"(ty) : "l"(a0));
        float inv = sInv[i], rh = sRhs[i];
        float2 r; r.x = fmaf(tx, inv, rh); r.y = fmaf(ty, inv, rh);
        sx2[sWoff[i] + pl] = r;
    }
    __syncthreads();

    // ---- level-scheduled solve (in place, half-warp per entry) ----
    int nlev = s_nlev;
    int hg = (w << 1) | h2;              // half-warp id 0..63
    for (int lev = 1; lev < nlev; lev++) {
        int s1 = sLvl[lev+1];
        for (int sl = sLvl[lev] + hg; sl < s1; sl += 64) {
            int i = sOrd[sl];
            int a = sLptr[i];
            int nIt = (sLptr[i+1] - a) >> 2;
            const uint2* ip = (const uint2*)(sLoff + a);
            ull a0 = 0, a1 = 0;
            for (int q = 0; q < nIt; q++) {
                uint2 pk = ip[q];
                fadd2(a0, sxp[pk.x & 0xFFFFu]);
                fadd2(a1, sxp[pk.x >> 16]);
                fadd2(a0, sxp[pk.y & 0xFFFFu]);
                fadd2(a1, sxp[pk.y >> 16]);
            }
            fadd2(a0, a1);
            float tx, ty;
            asm("mov.b64 {%0, %1}, %2;" : "=f"(tx), "=f"(ty) : "l"(a0));
            float inv = sInv[i];
            float2 c = sx2[sWoff[i] + pl];
            c.x = fmaf(tx, inv, c.x); c.y = fmaf(ty, inv, c.y);
            sx2[sWoff[i] + pl] = c;
        }
        __syncthreads();
    }

    // ---- copy out (tile holds final values) ----
    #pragma unroll
    for (int q = 0; q < 16; q++) {
        float2 t2 = sx2[tid*SROW2 + q];
        ob[(size_t)(2*q)*NN + tid]   = t2.x;
        ob[(size_t)(2*q+1)*NN + tid] = t2.y;
    }
}

// ---------------- launch ----------------
extern "C" void kernel_launch(void* const* d_in, const int* in_sizes, int n_in,
                              void* d_out, int out_size) {
    const float* x    = (const float*)d_in[0];
    const float* A    = (const float*)d_in[1];
    const int*   unk  = (const int*)  d_in[2];
    const float* mask = (const float*)d_in[3];
    float* out = (float*)d_out;

    const int SMEM = (NN+1)*SROW2*8                       // tile
                   + NU*4 + (NU/2)*4 + (NU+1)*4 + NU*4    // kptr,nit,lptr,ord
                   + (NU+1)*4 + NU*4*3                    // lvl,inv,rhs,woff
                   + KCAP*2 + LCAP*2;

    static bool attr_done = false;
    if (!attr_done) {
        cudaFuncSetAttribute(k_fused, cudaFuncAttributeMaxDynamicSharedMemorySize, SMEM);
        attr_done = true;
    }

    k_rank  <<<1, TPB>>>(unk);                 // launch 0
    k_row   <<<NU, 32>>>(A, unk);              // launch 1
    k_meta  <<<1, TPB>>>(unk, mask);           // launch 2
    k_fused <<<NP/PTS, TPB, SMEM>>>(x, out);   // launch 3 (ncu lands here)
}